// round 15
// baseline (speedup 1.0000x reference)
#include <cuda_runtime.h>
#include <cstdint>

#define GRID_D 128
#define NUM_CELLS (128*128*128)
#define INV_CELL 64.0f

// ---------------- zero kernel: flat one-shot, 32B stores, early trigger ------
// 2M cells * 16B = 32MB. Each thread zeroes 64B (2 x v8.b32) and immediately
// triggers PDL completion. Flat grid (no loop) minimizes time-to-last-trigger,
// which gates the p2g atomic release.
__global__ __launch_bounds__(256) void zero_kernel(float4* __restrict__ out)
{
    int t = blockIdx.x * blockDim.x + threadIdx.x;   // 512K threads, 64B each
    float4* p = out + 4ull * t;
    asm volatile(
        "st.global.v8.b32 [%0], {%1,%1,%1,%1,%1,%1,%1,%1};"
        :: "l"(p), "r"(0) : "memory");
    asm volatile(
        "st.global.v8.b32 [%0], {%1,%1,%1,%1,%1,%1,%1,%1};"
        :: "l"(p + 2), "r"(0) : "memory");
    cudaTriggerProgrammaticLaunchCompletion();
}

// 4 lanes per particle: dk = (lane>>1)&1 selects the z-corner, cp = lane&1
// selects the component pair ({m, m*vx} or {m*vy, m*vz}). Each lane issues 4
// red.global.add.v2.f32; the 4 lanes of a particle cover 32 contiguous bytes
// of out per RED warp-instruction. Pinned at the L2 atomic-sector floor
// (~6M 32B sector-RMWs). All loads + FMA work run BEFORE
// cudaGridDependencySynchronize so they overlap the zero kernel via PDL.
__global__ __launch_bounds__(256) void p2g_kernel(
    const float* __restrict__ pos,
    const float* __restrict__ vel,
    const float* __restrict__ mass,
    float* __restrict__ out,
    int n)
{
    int t = blockIdx.x * blockDim.x + threadIdx.x;
    int p  = t >> 2;          // particle index
    int dk = (t >> 1) & 1;    // z-corner
    int cp = t & 1;           // component pair
    if (p >= n) {
        cudaGridDependencySynchronize();
        return;
    }

    float rx = pos[3 * p + 0] * INV_CELL;
    float ry = pos[3 * p + 1] * INV_CELL;
    float rz = pos[3 * p + 2] * INV_CELL;

    float bx = floorf(rx), by = floorf(ry), bz = floorf(rz);
    int ix = (int)bx, iy = (int)by, iz = (int)bz;

    float fx = rx - bx, fy = ry - by, fz = rz - bz;
    float wx[2] = {1.0f - fx, fx};
    float wy[2] = {1.0f - fy, fy};
    float wzk   = dk ? fz : (1.0f - fz);

    float m = mass[p];
    float c0, c1;
    if (cp == 0) { c0 = m;                  c1 = m * vel[3 * p + 0]; }
    else         { c0 = m * vel[3 * p + 1]; c1 = m * vel[3 * p + 2]; }
    c0 *= wzk;
    c1 *= wzk;

    int h0 = (iz + dk) + ix * GRID_D + iy * (GRID_D * GRID_D);
    float* base_ptr = out + 4ull * (unsigned)h0 + 2 * cp;

    // pre-compute all payloads so every load/FMA is issued pre-sync
    float w00 = wx[0] * wy[0], w10 = wx[1] * wy[0];
    float w01 = wx[0] * wy[1], w11 = wx[1] * wy[1];
    float a00_0 = w00 * c0, a00_1 = w00 * c1;
    float a10_0 = w10 * c0, a10_1 = w10 * c1;
    float a01_0 = w01 * c0, a01_1 = w01 * c1;
    float a11_0 = w11 * c0, a11_1 = w11 * c1;

    // wait for zero_kernel's memory to be visible, then fire the atomics
    cudaGridDependencySynchronize();

    float* p00 = base_ptr;
    float* p10 = base_ptr + 4ull * GRID_D;
    float* p01 = base_ptr + 4ull * (GRID_D * GRID_D);
    float* p11 = base_ptr + 4ull * (GRID_D + GRID_D * GRID_D);
    asm volatile("red.global.add.v2.f32 [%0], {%1, %2};" :: "l"(p00), "f"(a00_0), "f"(a00_1) : "memory");
    asm volatile("red.global.add.v2.f32 [%0], {%1, %2};" :: "l"(p10), "f"(a10_0), "f"(a10_1) : "memory");
    asm volatile("red.global.add.v2.f32 [%0], {%1, %2};" :: "l"(p01), "f"(a01_0), "f"(a01_1) : "memory");
    asm volatile("red.global.add.v2.f32 [%0], {%1, %2};" :: "l"(p11), "f"(a11_0), "f"(a11_1) : "memory");
}

extern "C" void kernel_launch(void* const* d_in, const int* in_sizes, int n_in,
                              void* d_out, int out_size)
{
    const float* pos  = (const float*)d_in[0];
    const float* vel  = (const float*)d_in[1];
    const float* mass = (const float*)d_in[2];
    float* out = (float*)d_out;
    int n = in_sizes[2];   // NUM_POINTS

    // flat zero of the 32MB output (stays L2-resident for the atomics)
    zero_kernel<<<NUM_CELLS / (4 * 256), 256>>>((float4*)out);

    // p2g with programmatic stream serialization: launches while zero drains;
    // atomics held back by cudaGridDependencySynchronize.
    int threads = 256;
    long long total = 4LL * n;               // 4 lanes per particle
    int blocks = (int)((total + threads - 1) / threads);

    cudaLaunchConfig_t cfg = {};
    cfg.gridDim  = dim3((unsigned)blocks, 1, 1);
    cfg.blockDim = dim3((unsigned)threads, 1, 1);
    cfg.dynamicSmemBytes = 0;
    cfg.stream = 0;
    cudaLaunchAttribute attrs[1];
    attrs[0].id = cudaLaunchAttributeProgrammaticStreamSerialization;
    attrs[0].val.programmaticStreamSerializationAllowed = 1;
    cfg.attrs = attrs;
    cfg.numAttrs = 1;

    cudaLaunchKernelEx(&cfg, p2g_kernel, pos, vel, mass, out, n);
}

// round 16
// speedup vs baseline: 1.0508x; 1.0508x over previous
#include <cuda_runtime.h>
#include <cstdint>

#define GRID_D 128
#define NUM_CELLS (128*128*128)
#define INV_CELL 64.0f

// ---------------- zero kernel: ONE 32B store per thread, then trigger --------
// 2M cells * 16B = 32MB. 2048 CTAs x 512 threads x 32B. PDL only guarantees
// visibility of pre-trigger writes, so minimizing pre-trigger work per thread
// (a single v8.b32) minimizes time-to-last-trigger, which gates the p2g
// atomic release.
__global__ __launch_bounds__(512) void zero_kernel(float4* __restrict__ out)
{
    int t = blockIdx.x * blockDim.x + threadIdx.x;   // 1M threads, 32B each
    float4* p = out + 2ull * t;
    asm volatile(
        "st.global.v8.b32 [%0], {%1,%1,%1,%1,%1,%1,%1,%1};"
        :: "l"(p), "r"(0) : "memory");
    cudaTriggerProgrammaticLaunchCompletion();
}

// 4 lanes per particle: dk = (lane>>1)&1 selects the z-corner, cp = lane&1
// selects the component pair ({m, m*vx} or {m*vy, m*vz}). Each lane issues 4
// red.global.add.v2.f32; the 4 lanes of a particle cover 32 contiguous bytes
// of out per RED warp-instruction. Pinned at the L2 atomic-sector floor
// (~6M 32B sector-RMWs). All loads + FMA work run BEFORE
// cudaGridDependencySynchronize so they overlap the zero kernel via PDL.
__global__ __launch_bounds__(256) void p2g_kernel(
    const float* __restrict__ pos,
    const float* __restrict__ vel,
    const float* __restrict__ mass,
    float* __restrict__ out,
    int n)
{
    int t = blockIdx.x * blockDim.x + threadIdx.x;
    int p  = t >> 2;          // particle index
    int dk = (t >> 1) & 1;    // z-corner
    int cp = t & 1;           // component pair
    if (p >= n) {
        cudaGridDependencySynchronize();
        return;
    }

    float rx = pos[3 * p + 0] * INV_CELL;
    float ry = pos[3 * p + 1] * INV_CELL;
    float rz = pos[3 * p + 2] * INV_CELL;

    float bx = floorf(rx), by = floorf(ry), bz = floorf(rz);
    int ix = (int)bx, iy = (int)by, iz = (int)bz;

    float fx = rx - bx, fy = ry - by, fz = rz - bz;
    float wx[2] = {1.0f - fx, fx};
    float wy[2] = {1.0f - fy, fy};
    float wzk   = dk ? fz : (1.0f - fz);

    float m = mass[p];
    float c0, c1;
    if (cp == 0) { c0 = m;                  c1 = m * vel[3 * p + 0]; }
    else         { c0 = m * vel[3 * p + 1]; c1 = m * vel[3 * p + 2]; }
    c0 *= wzk;
    c1 *= wzk;

    int h0 = (iz + dk) + ix * GRID_D + iy * (GRID_D * GRID_D);
    float* base_ptr = out + 4ull * (unsigned)h0 + 2 * cp;

    // pre-compute all payloads so every load/FMA is issued pre-sync
    float w00 = wx[0] * wy[0], w10 = wx[1] * wy[0];
    float w01 = wx[0] * wy[1], w11 = wx[1] * wy[1];
    float a00_0 = w00 * c0, a00_1 = w00 * c1;
    float a10_0 = w10 * c0, a10_1 = w10 * c1;
    float a01_0 = w01 * c0, a01_1 = w01 * c1;
    float a11_0 = w11 * c0, a11_1 = w11 * c1;

    // wait for zero_kernel's memory to be visible, then fire the atomics
    cudaGridDependencySynchronize();

    float* p00 = base_ptr;
    float* p10 = base_ptr + 4ull * GRID_D;
    float* p01 = base_ptr + 4ull * (GRID_D * GRID_D);
    float* p11 = base_ptr + 4ull * (GRID_D + GRID_D * GRID_D);
    asm volatile("red.global.add.v2.f32 [%0], {%1, %2};" :: "l"(p00), "f"(a00_0), "f"(a00_1) : "memory");
    asm volatile("red.global.add.v2.f32 [%0], {%1, %2};" :: "l"(p10), "f"(a10_0), "f"(a10_1) : "memory");
    asm volatile("red.global.add.v2.f32 [%0], {%1, %2};" :: "l"(p01), "f"(a01_0), "f"(a01_1) : "memory");
    asm volatile("red.global.add.v2.f32 [%0], {%1, %2};" :: "l"(p11), "f"(a11_0), "f"(a11_1) : "memory");
}

extern "C" void kernel_launch(void* const* d_in, const int* in_sizes, int n_in,
                              void* d_out, int out_size)
{
    const float* pos  = (const float*)d_in[0];
    const float* vel  = (const float*)d_in[1];
    const float* mass = (const float*)d_in[2];
    float* out = (float*)d_out;
    int n = in_sizes[2];   // NUM_POINTS

    // flat zero of the 32MB output: 1M threads x 32B, trigger after 1 store
    zero_kernel<<<NUM_CELLS / (2 * 512), 512>>>((float4*)out);

    // p2g with programmatic stream serialization: launches while zero drains;
    // atomics held back by cudaGridDependencySynchronize.
    int threads = 256;
    long long total = 4LL * n;               // 4 lanes per particle
    int blocks = (int)((total + threads - 1) / threads);

    cudaLaunchConfig_t cfg = {};
    cfg.gridDim  = dim3((unsigned)blocks, 1, 1);
    cfg.blockDim = dim3((unsigned)threads, 1, 1);
    cfg.dynamicSmemBytes = 0;
    cfg.stream = 0;
    cudaLaunchAttribute attrs[1];
    attrs[0].id = cudaLaunchAttributeProgrammaticStreamSerialization;
    attrs[0].val.programmaticStreamSerializationAllowed = 1;
    cfg.attrs = attrs;
    cfg.numAttrs = 1;

    cudaLaunchKernelEx(&cfg, p2g_kernel, pos, vel, mass, out, n);
}

// round 17
// speedup vs baseline: 1.0525x; 1.0016x over previous
#include <cuda_runtime.h>
#include <cstdint>

#define GRID_D 128
#define NUM_CELLS (128*128*128)
#define INV_CELL 64.0f

// ---------------- zero kernel: ONE 32B store per thread, then trigger --------
// 2M cells * 16B = 32MB. 2048 CTAs x 512 threads x 32B. PDL guarantees
// visibility only for pre-trigger writes, so a single v8.b32 store before the
// trigger minimizes time-to-last-trigger, which gates the p2g atomic release.
// Wide stores leave the output L2-resident for the subsequent atomics.
__global__ __launch_bounds__(512) void zero_kernel(float4* __restrict__ out)
{
    int t = blockIdx.x * blockDim.x + threadIdx.x;   // 1M threads, 32B each
    float4* p = out + 2ull * t;
    asm volatile(
        "st.global.v8.b32 [%0], {%1,%1,%1,%1,%1,%1,%1,%1};"
        :: "l"(p), "r"(0) : "memory");
    cudaTriggerProgrammaticLaunchCompletion();
}

// 4 lanes per particle: dk = (lane>>1)&1 selects the z-corner, cp = lane&1
// selects the component pair ({m, m*vx} or {m*vy, m*vz}). Each lane issues 4
// red.global.add.v2.f32; the 4 lanes of a particle cover 32 contiguous bytes
// of out per RED warp-instruction, minimizing per-instruction sector count.
// The kernel is pinned at the L2 atomic-sector floor (~6M 32B sector-RMWs
// ~= 37.5us) — verified invariant across four RED mapping variants. All loads
// and FMA work run BEFORE cudaGridDependencySynchronize so they overlap the
// zero kernel via programmatic dependent launch.
__global__ __launch_bounds__(256) void p2g_kernel(
    const float* __restrict__ pos,
    const float* __restrict__ vel,
    const float* __restrict__ mass,
    float* __restrict__ out,
    int n)
{
    int t = blockIdx.x * blockDim.x + threadIdx.x;
    int p  = t >> 2;          // particle index
    int dk = (t >> 1) & 1;    // z-corner
    int cp = t & 1;           // component pair
    if (p >= n) {
        cudaGridDependencySynchronize();
        return;
    }

    float rx = pos[3 * p + 0] * INV_CELL;
    float ry = pos[3 * p + 1] * INV_CELL;
    float rz = pos[3 * p + 2] * INV_CELL;

    float bx = floorf(rx), by = floorf(ry), bz = floorf(rz);
    int ix = (int)bx, iy = (int)by, iz = (int)bz;

    float fx = rx - bx, fy = ry - by, fz = rz - bz;
    float wx[2] = {1.0f - fx, fx};
    float wy[2] = {1.0f - fy, fy};
    float wzk   = dk ? fz : (1.0f - fz);

    float m = mass[p];
    float c0, c1;
    if (cp == 0) { c0 = m;                  c1 = m * vel[3 * p + 0]; }
    else         { c0 = m * vel[3 * p + 1]; c1 = m * vel[3 * p + 2]; }
    c0 *= wzk;
    c1 *= wzk;

    int h0 = (iz + dk) + ix * GRID_D + iy * (GRID_D * GRID_D);
    float* base_ptr = out + 4ull * (unsigned)h0 + 2 * cp;

    // pre-compute all payloads so every load/FMA is issued pre-sync
    float w00 = wx[0] * wy[0], w10 = wx[1] * wy[0];
    float w01 = wx[0] * wy[1], w11 = wx[1] * wy[1];
    float a00_0 = w00 * c0, a00_1 = w00 * c1;
    float a10_0 = w10 * c0, a10_1 = w10 * c1;
    float a01_0 = w01 * c0, a01_1 = w01 * c1;
    float a11_0 = w11 * c0, a11_1 = w11 * c1;

    // wait for zero_kernel's memory to be visible, then fire the atomics
    cudaGridDependencySynchronize();

    float* p00 = base_ptr;
    float* p10 = base_ptr + 4ull * GRID_D;
    float* p01 = base_ptr + 4ull * (GRID_D * GRID_D);
    float* p11 = base_ptr + 4ull * (GRID_D + GRID_D * GRID_D);
    asm volatile("red.global.add.v2.f32 [%0], {%1, %2};" :: "l"(p00), "f"(a00_0), "f"(a00_1) : "memory");
    asm volatile("red.global.add.v2.f32 [%0], {%1, %2};" :: "l"(p10), "f"(a10_0), "f"(a10_1) : "memory");
    asm volatile("red.global.add.v2.f32 [%0], {%1, %2};" :: "l"(p01), "f"(a01_0), "f"(a01_1) : "memory");
    asm volatile("red.global.add.v2.f32 [%0], {%1, %2};" :: "l"(p11), "f"(a11_0), "f"(a11_1) : "memory");
}

extern "C" void kernel_launch(void* const* d_in, const int* in_sizes, int n_in,
                              void* d_out, int out_size)
{
    const float* pos  = (const float*)d_in[0];
    const float* vel  = (const float*)d_in[1];
    const float* mass = (const float*)d_in[2];
    float* out = (float*)d_out;
    int n = in_sizes[2];   // NUM_POINTS

    // flat zero of the 32MB output: 1M threads x 32B, trigger after 1 store
    zero_kernel<<<NUM_CELLS / (2 * 512), 512>>>((float4*)out);

    // p2g with programmatic stream serialization: launches while zero drains;
    // atomics held back by cudaGridDependencySynchronize.
    int threads = 256;
    long long total = 4LL * n;               // 4 lanes per particle
    int blocks = (int)((total + threads - 1) / threads);

    cudaLaunchConfig_t cfg = {};
    cfg.gridDim  = dim3((unsigned)blocks, 1, 1);
    cfg.blockDim = dim3((unsigned)threads, 1, 1);
    cfg.dynamicSmemBytes = 0;
    cfg.stream = 0;
    cudaLaunchAttribute attrs[1];
    attrs[0].id = cudaLaunchAttributeProgrammaticStreamSerialization;
    attrs[0].val.programmaticStreamSerializationAllowed = 1;
    cfg.attrs = attrs;
    cfg.numAttrs = 1;

    cudaLaunchKernelEx(&cfg, p2g_kernel, pos, vel, mass, out, n);
}